// round 1
// baseline (speedup 1.0000x reference)
#include <cuda_runtime.h>
#include <math.h>

#define NQ 12
#define DIM (1 << NQ)          // 4096 amplitudes
#define NPAIR (DIM / 2)        // 2048 pairs per 1q gate
#define NL 4
#define NC 10
#define BATCH 512
#define TPB 256
#define BN_EPS 1e-5f

// Scratch for softmax probs (B x NC). __device__ global: allocation-free.
__device__ float g_probs[BATCH * NC];

__global__ __launch_bounds__(TPB) void vqc_kernel(const float* __restrict__ x,
                                                  const float* __restrict__ w,
                                                  const float* __restrict__ bias) {
    __shared__ float sre[DIM];
    __shared__ float sim[DIM];
    __shared__ float s_ez[NC];

    const int b = blockIdx.x;
    const int tid = threadIdx.x;

    // |0...0>
    for (int i = tid; i < DIM; i += TPB) {
        sre[i] = (i == 0) ? 1.0f : 0.0f;
        sim[i] = 0.0f;
    }
    if (tid < NC) s_ez[tid] = 0.0f;

    // half-angles for RY embedding for this sample
    float xh[NQ];
#pragma unroll
    for (int q = 0; q < NQ; q++) xh[q] = 0.5f * x[b * NQ + q];
    __syncthreads();

    for (int l = 0; l < NL; l++) {
        // ---- fused RY(x_q) followed by Rot(phi,theta,omega): U = Rot @ RY ----
        for (int q = 0; q < NQ; q++) {
            float sy, cy;
            sincosf(xh[q], &sy, &cy);

            const float phi = w[(l * NQ + q) * 3 + 0];
            const float th  = w[(l * NQ + q) * 3 + 1];
            const float om  = w[(l * NQ + q) * 3 + 2];
            float st, ct;
            sincosf(0.5f * th, &st, &ct);
            const float a1 = -0.5f * (phi + om);   // R00 = e^{i a1} ct
            const float a2 =  0.5f * (phi - om);   // R01 = -e^{i a2} st
            float s1, c1, s2, c2;
            sincosf(a1, &s1, &c1);
            sincosf(a2, &s2, &c2);

            const float R00r =  c1 * ct, R00i =  s1 * ct;
            const float R01r = -c2 * st, R01i = -s2 * st;
            const float R10r =  c2 * st, R10i = -s2 * st;
            const float R11r =  c1 * ct, R11i = -s1 * ct;

            // U = R * [[cy,-sy],[sy,cy]]
            const float U00r =  R00r * cy + R01r * sy, U00i =  R00i * cy + R01i * sy;
            const float U01r = -R00r * sy + R01r * cy, U01i = -R00i * sy + R01i * cy;
            const float U10r =  R10r * cy + R11r * sy, U10i =  R10i * cy + R11i * sy;
            const float U11r = -R10r * sy + R11r * cy, U11i = -R10i * sy + R11i * cy;

            const int bit = NQ - 1 - q;
            const int stride = 1 << bit;
#pragma unroll 4
            for (int p = tid; p < NPAIR; p += TPB) {
                const int i0 = ((p >> bit) << (bit + 1)) | (p & (stride - 1));
                const int i1 = i0 | stride;
                const float a0r = sre[i0], a0i = sim[i0];
                const float a1r = sre[i1], a1i = sim[i1];
                sre[i0] = U00r * a0r - U00i * a0i + U01r * a1r - U01i * a1i;
                sim[i0] = U00r * a0i + U00i * a0r + U01r * a1i + U01i * a1r;
                sre[i1] = U10r * a0r - U10i * a0i + U11r * a1r - U11i * a1i;
                sim[i1] = U10r * a0i + U10i * a0r + U11r * a1i + U11i * a1r;
            }
            __syncthreads();
        }

        // ---- ring of CNOTs: ctrl=q, tgt=(q+1)%NQ ----
        for (int q = 0; q < NQ; q++) {
            const int ctrl = q, tgt = (q + 1) % NQ;
            const int bc = NQ - 1 - ctrl, bt = NQ - 1 - tgt;
            const int hi = bc > bt ? bc : bt;
            const int lo = bc > bt ? bt : bc;
#pragma unroll 4
            for (int p = tid; p < DIM / 4; p += TPB) {
                int m = p;
                m = ((m >> lo) << (lo + 1)) | (m & ((1 << lo) - 1));
                m = ((m >> hi) << (hi + 1)) | (m & ((1 << hi) - 1));
                const int i = m | (1 << bc);       // ctrl=1, tgt=0
                const int j = i | (1 << bt);       // ctrl=1, tgt=1
                const float tr = sre[i], ti = sim[i];
                sre[i] = sre[j]; sim[i] = sim[j];
                sre[j] = tr;     sim[j] = ti;
            }
            __syncthreads();
        }
    }

    // ---- <Z_i> for i = 0..9 ----
    float ez[NC];
#pragma unroll
    for (int c = 0; c < NC; c++) ez[c] = 0.0f;
    for (int i = tid; i < DIM; i += TPB) {
        const float p = sre[i] * sre[i] + sim[i] * sim[i];
#pragma unroll
        for (int c = 0; c < NC; c++)
            ez[c] += ((i >> (NQ - 1 - c)) & 1) ? -p : p;
    }
#pragma unroll
    for (int c = 0; c < NC; c++) {
        float v = ez[c];
        for (int o = 16; o > 0; o >>= 1) v += __shfl_down_sync(0xffffffffu, v, o);
        if ((tid & 31) == 0) atomicAdd(&s_ez[c], v);
    }
    __syncthreads();

    // ---- softmax(expz + bias) -> g_probs ----
    if (tid == 0) {
        float z[NC];
        float m = -1e30f;
#pragma unroll
        for (int c = 0; c < NC; c++) {
            z[c] = s_ez[c] + bias[c];
            m = fmaxf(m, z[c]);
        }
        float sum = 0.0f;
#pragma unroll
        for (int c = 0; c < NC; c++) {
            z[c] = expf(z[c] - m);
            sum += z[c];
        }
        const float inv = 1.0f / sum;
#pragma unroll
        for (int c = 0; c < NC; c++) g_probs[b * NC + c] = z[c] * inv;
    }
}

// BatchNorm1d over the batch, per class. 10 blocks x 512 threads.
__global__ __launch_bounds__(BATCH) void bn_kernel(const float* __restrict__ gamma,
                                                   const float* __restrict__ beta,
                                                   float* __restrict__ out) {
    const int c = blockIdx.x;
    const int t = threadIdx.x;  // = batch index

    const float p = g_probs[t * NC + c];

    __shared__ float ssum[BATCH / 32];
    __shared__ float ssq[BATCH / 32];
    float s = p, q = p * p;
    for (int o = 16; o > 0; o >>= 1) {
        s += __shfl_down_sync(0xffffffffu, s, o);
        q += __shfl_down_sync(0xffffffffu, q, o);
    }
    if ((t & 31) == 0) {
        ssum[t >> 5] = s;
        ssq[t >> 5] = q;
    }
    __syncthreads();

    __shared__ float smu, srstd;
    if (t == 0) {
        float S = 0.0f, Q = 0.0f;
#pragma unroll
        for (int i = 0; i < BATCH / 32; i++) { S += ssum[i]; Q += ssq[i]; }
        const float mu = S / (float)BATCH;
        const float var = Q / (float)BATCH - mu * mu;
        smu = mu;
        srstd = rsqrtf(var + BN_EPS);
    }
    __syncthreads();

    out[t * NC + c] = (p - smu) * srstd * gamma[c] + beta[c];
}

extern "C" void kernel_launch(void* const* d_in, const int* in_sizes, int n_in,
                              void* d_out, int out_size) {
    const float* x      = (const float*)d_in[0];  // (512, 12)
    const float* wts    = (const float*)d_in[1];  // (4, 12, 3)
    const float* bias   = (const float*)d_in[2];  // (10,)
    const float* gamma  = (const float*)d_in[3];  // (10,)
    const float* beta   = (const float*)d_in[4];  // (10,)
    float* out = (float*)d_out;                   // (512, 10)

    vqc_kernel<<<BATCH, TPB>>>(x, wts, bias);
    bn_kernel<<<NC, BATCH>>>(gamma, beta, out);
}

// round 3
// speedup vs baseline: 1.3634x; 1.3634x over previous
#include <cuda_runtime.h>
#include <math.h>

#define NQ 12
#define DIM 4096
#define QUADS 1024
#define NL 4
#define NC 10
#define BATCH 512
#define TPB 256
#define BN_EPS 1e-5f
#define NSWEEP (NL * NQ / 2)   // 24

// Scratch for softmax probs (B x NC). __device__ global: allocation-free.
__device__ float g_probs[BATCH * NC];

// storage swizzle: amplitude i lives at slot i ^ (i>>4)  (bijective on 12 bits)
__device__ __forceinline__ int sw(int i) { return i ^ (i >> 4); }

// apply 2x2 complex gate g to the amplitude pair (a, b) in-place
__device__ __forceinline__ void gate2(const float2 g0, const float2 g1,
                                      const float2 g2, const float2 g3,
                                      float2& a, float2& b) {
    float2 na, nb;
    na.x = g0.x * a.x - g0.y * a.y + g1.x * b.x - g1.y * b.y;
    na.y = g0.x * a.y + g0.y * a.x + g1.x * b.y + g1.y * b.x;
    nb.x = g2.x * a.x - g2.y * a.y + g3.x * b.x - g3.y * b.y;
    nb.y = g2.x * a.y + g2.y * a.x + g3.x * b.y + g3.y * b.x;
    a = na; b = nb;
}

__global__ __launch_bounds__(TPB) void vqc_kernel(const float* __restrict__ x,
                                                  const float* __restrict__ w,
                                                  const float* __restrict__ bias) {
    __shared__ float2 st[DIM];                 // state, swizzled slots
    __shared__ float2 s_g[NL * NQ][4];         // fused RY*Rot 2x2 gates
    __shared__ int    s_Mp[NL + 1][NQ];        // rows of M^l, l = 0..4
    __shared__ int    s_Mip[NL][NQ];           // rows of M^{-l}, l = 0..3
    __shared__ int    s_sp[NSWEEP][12];        // per sweep: v1, v2, bas[0..9]
    __shared__ float  s_ez[NC];

    const int b = blockIdx.x;
    const int tid = threadIdx.x;

    // ---- phase A: init state, GF(2) ring matrices, fused gate matrices ----
    for (int i = tid; i < DIM; i += TPB)
        st[i] = make_float2(i == 0 ? 1.0f : 0.0f, 0.0f);   // sw(0)==0
    if (tid < NC) s_ez[tid] = 0.0f;

    if (tid == 0) {
        // ring map M (amplitude perm C|i> = |M i>), built in application order
        int M[NQ], Mi[NQ];
        for (int r = 0; r < NQ; r++) { M[r] = 1 << r; Mi[r] = 1 << r; }
        for (int q = 0; q < NQ; q++) {           // CNOT(q, q+1), q ascending
            int pc = NQ - 1 - q, pt = NQ - 1 - ((q + 1) % NQ);
            M[pt] ^= M[pc];
        }
        for (int q = NQ - 1; q >= 0; q--) {      // inverse: reversed order
            int pc = NQ - 1 - q, pt = NQ - 1 - ((q + 1) % NQ);
            Mi[pt] ^= Mi[pc];
        }
        // powers M^l and M^{-l}
        int P[NQ], Pi[NQ];
        for (int r = 0; r < NQ; r++) { P[r] = 1 << r; Pi[r] = 1 << r; }
        for (int l = 0; l <= NL; l++) {
            for (int r = 0; r < NQ; r++) s_Mp[l][r] = P[r];
            if (l < NL) for (int r = 0; r < NQ; r++) s_Mip[l][r] = Pi[r];
            int Pn[NQ], Pin[NQ];
            for (int r = 0; r < NQ; r++) {
                int acc = 0, acci = 0;
                for (int s = 0; s < NQ; s++) {
                    if ((M[r]  >> s) & 1) acc  ^= P[s];
                    if ((Mi[r] >> s) & 1) acci ^= Pi[s];
                }
                Pn[r] = acc; Pin[r] = acci;
            }
            for (int r = 0; r < NQ; r++) { P[r] = Pn[r]; Pi[r] = Pin[r]; }
        }
    }

    if (tid < NL * NQ) {   // fused gate U = Rot(w) @ RY(x)
        const int l = tid / NQ, q = tid % NQ;
        const float xh = 0.5f * x[b * NQ + q];
        float sy, cy; sincosf(xh, &sy, &cy);
        const float phi = w[(l * NQ + q) * 3 + 0];
        const float th  = w[(l * NQ + q) * 3 + 1];
        const float om  = w[(l * NQ + q) * 3 + 2];
        float stt, ct; sincosf(0.5f * th, &stt, &ct);
        const float a1 = -0.5f * (phi + om);
        const float a2 =  0.5f * (phi - om);
        float s1, c1, s2, c2;
        sincosf(a1, &s1, &c1);
        sincosf(a2, &s2, &c2);
        const float R00r =  c1 * ct, R00i =  s1 * ct;
        const float R01r = -c2 * stt, R01i = -s2 * stt;
        const float R10r =  c2 * stt, R10i = -s2 * stt;
        const float R11r =  c1 * ct, R11i = -s1 * ct;
        s_g[tid][0] = make_float2( R00r * cy + R01r * sy,  R00i * cy + R01i * sy);
        s_g[tid][1] = make_float2(-R00r * sy + R01r * cy, -R00i * sy + R01i * cy);
        s_g[tid][2] = make_float2( R10r * cy + R11r * sy,  R10i * cy + R11i * sy);
        s_g[tid][3] = make_float2(-R10r * sy + R11r * cy, -R10i * sy + R11i * cy);
    }
    __syncthreads();

    // ---- phase B: per-sweep params (masks + null-space basis) ----
    if (tid < NSWEEP) {
        const int l = tid / 6, k = tid % 6;
        const int pa = NQ - 1 - 2 * k;           // bit of qubit 2k
        const int pb = NQ - 1 - (2 * k + 1);     // bit of qubit 2k+1
        int v1 = 0, v2 = 0;                      // columns of M^{-l}
        for (int r = 0; r < NQ; r++) {
            v1 |= ((s_Mip[l][r] >> pa) & 1) << r;
            v2 |= ((s_Mip[l][r] >> pb) & 1) << r;
        }
        int D1 = s_Mp[l][pa], D2 = s_Mp[l][pb];  // duals: rows of M^l
        const int p1 = __ffs(D1) - 1;
        if ((D2 >> p1) & 1) D2 ^= D1;
        const int p2 = __ffs(D2) - 1;
        if ((D1 >> p2) & 1) D1 ^= D2;
        s_sp[tid][0] = v1;
        s_sp[tid][1] = v2;
        int freeb = 0xFFF & ~((1 << p1) | (1 << p2));
        for (int jj = 0; jj < 10; jj++) {
            const int j = __ffs(freeb) - 1; freeb &= freeb - 1;
            s_sp[tid][2 + jj] = (1 << j) ^ (((D1 >> j) & 1) << p1)
                                         ^ (((D2 >> j) & 1) << p2);
        }
    }
    __syncthreads();

    // ---- phase C: 24 two-qubit sweeps (CNOT rings folded into masks) ----
    for (int swp = 0; swp < NSWEEP; swp++) {
        const int l = swp / 6, k = swp % 6;
        const int v1 = s_sp[swp][0];
        const int v2 = s_sp[swp][1];
        // base index for t = tid (lane bits 0..7 of t)
        int i0b = 0;
#pragma unroll
        for (int jj = 0; jj < 8; jj++)
            i0b ^= ((tid >> jj) & 1) ? s_sp[swp][2 + jj] : 0;
        const int bas8 = s_sp[swp][10], bas9 = s_sp[swp][11];

        const float2* Ga = s_g[l * NQ + 2 * k];
        const float2* Gb = s_g[l * NQ + 2 * k + 1];
        const float2 a0 = Ga[0], a1 = Ga[1], a2 = Ga[2], a3 = Ga[3];
        const float2 b0 = Gb[0], b1 = Gb[1], b2 = Gb[2], b3 = Gb[3];

#pragma unroll
        for (int u = 0; u < QUADS / TPB; u++) {
            const int i0 = i0b ^ ((u & 1) ? bas8 : 0) ^ ((u & 2) ? bas9 : 0);
            const int j00 = sw(i0);
            const int j01 = sw(i0 ^ v2);
            const int j10 = sw(i0 ^ v1);
            const int j11 = sw(i0 ^ v1 ^ v2);
            float2 s00 = st[j00], s01 = st[j01], s10 = st[j10], s11 = st[j11];
            gate2(b0, b1, b2, b3, s00, s01);   // U_b on qubit 2k+1
            gate2(b0, b1, b2, b3, s10, s11);
            gate2(a0, a1, a2, a3, s00, s10);   // U_a on qubit 2k
            gate2(a0, a1, a2, a3, s01, s11);
            st[j00] = s00; st[j01] = s01; st[j10] = s10; st[j11] = s11;
        }
        __syncthreads();
    }

    // ---- measurement: <Z_c> with the final C^4 folded in as parity masks ----
    int dz[NC];
#pragma unroll
    for (int c = 0; c < NC; c++) dz[c] = s_Mp[NL][NQ - 1 - c];

    float ez[NC];
#pragma unroll
    for (int c = 0; c < NC; c++) ez[c] = 0.0f;
    for (int i = tid; i < DIM; i += TPB) {
        const float2 a = st[sw(i)];
        const float p = a.x * a.x + a.y * a.y;
#pragma unroll
        for (int c = 0; c < NC; c++)
            ez[c] += (__popc(i & dz[c]) & 1) ? -p : p;
    }
#pragma unroll
    for (int c = 0; c < NC; c++) {
        float v = ez[c];
        for (int o = 16; o > 0; o >>= 1) v += __shfl_down_sync(0xffffffffu, v, o);
        if ((tid & 31) == 0) atomicAdd(&s_ez[c], v);
    }
    __syncthreads();

    // ---- softmax(expz + bias) -> g_probs ----
    if (tid == 0) {
        float z[NC];
        float m = -1e30f;
#pragma unroll
        for (int c = 0; c < NC; c++) {
            z[c] = s_ez[c] + bias[c];
            m = fmaxf(m, z[c]);
        }
        float sum = 0.0f;
#pragma unroll
        for (int c = 0; c < NC; c++) {
            z[c] = expf(z[c] - m);
            sum += z[c];
        }
        const float inv = 1.0f / sum;
#pragma unroll
        for (int c = 0; c < NC; c++) g_probs[b * NC + c] = z[c] * inv;
    }
}

// BatchNorm1d over the batch, per class. 10 blocks x 512 threads.
__global__ __launch_bounds__(BATCH) void bn_kernel(const float* __restrict__ gamma,
                                                   const float* __restrict__ beta,
                                                   float* __restrict__ out) {
    const int c = blockIdx.x;
    const int t = threadIdx.x;  // = batch index

    const float p = g_probs[t * NC + c];

    __shared__ float ssum[BATCH / 32];
    __shared__ float ssq[BATCH / 32];
    float s = p, q = p * p;
    for (int o = 16; o > 0; o >>= 1) {
        s += __shfl_down_sync(0xffffffffu, s, o);
        q += __shfl_down_sync(0xffffffffu, q, o);
    }
    if ((t & 31) == 0) {
        ssum[t >> 5] = s;
        ssq[t >> 5] = q;
    }
    __syncthreads();

    __shared__ float smu, srstd;
    if (t == 0) {
        float S = 0.0f, Q = 0.0f;
#pragma unroll
        for (int i = 0; i < BATCH / 32; i++) { S += ssum[i]; Q += ssq[i]; }
        const float mu = S / (float)BATCH;
        const float var = Q / (float)BATCH - mu * mu;
        smu = mu;
        srstd = rsqrtf(var + BN_EPS);
    }
    __syncthreads();

    out[t * NC + c] = (p - smu) * srstd * gamma[c] + beta[c];
}

extern "C" void kernel_launch(void* const* d_in, const int* in_sizes, int n_in,
                              void* d_out, int out_size) {
    const float* x      = (const float*)d_in[0];  // (512, 12)
    const float* wts    = (const float*)d_in[1];  // (4, 12, 3)
    const float* bias   = (const float*)d_in[2];  // (10,)
    const float* gamma  = (const float*)d_in[3];  // (10,)
    const float* beta   = (const float*)d_in[4];  // (10,)
    float* out = (float*)d_out;                   // (512, 10)

    vqc_kernel<<<BATCH, TPB>>>(x, wts, bias);
    bn_kernel<<<NC, BATCH>>>(gamma, beta, out);
}

// round 4
// speedup vs baseline: 2.2248x; 1.6318x over previous
#include <cuda_runtime.h>
#include <math.h>

#define NQ 12
#define DIM 4096
#define QUADS 1024
#define NL 4
#define NC 10
#define BATCH 512
#define TPB 256
#define BN_EPS 1e-5f
#define NSWEEP (NL * NQ / 2)   // 24

// Scratch for softmax probs (B x NC). __device__ global: allocation-free.
__device__ float g_probs[BATCH * NC];

// storage swizzle: amplitude i lives at slot i ^ (i>>4)  (bijective, XOR-linear)
__device__ __forceinline__ int sw(int i) { return i ^ (i >> 4); }

// apply 2x2 complex gate g to the amplitude pair (a, b) in-place
__device__ __forceinline__ void gate2(const float2 g0, const float2 g1,
                                      const float2 g2, const float2 g3,
                                      float2& a, float2& b) {
    float2 na, nb;
    na.x = g0.x * a.x - g0.y * a.y + g1.x * b.x - g1.y * b.y;
    na.y = g0.x * a.y + g0.y * a.x + g1.x * b.y + g1.y * b.x;
    nb.x = g2.x * a.x - g2.y * a.y + g3.x * b.x - g3.y * b.y;
    nb.y = g2.x * a.y + g2.y * a.x + g3.x * b.y + g3.y * b.x;
    a = na; b = nb;
}

__global__ __launch_bounds__(TPB, 4) void vqc_kernel(const float* __restrict__ x,
                                                     const float* __restrict__ w,
                                                     const float* __restrict__ bias) {
    __shared__ float2 st[DIM];                 // state, swizzled slots
    __shared__ float2 s_g[NL * NQ][4];         // fused RY*Rot 2x2 gates
    __shared__ int    s_Mp[NL + 1][NQ];        // rows of M^l, l = 0..4
    __shared__ int    s_Mip[NL][NQ];           // rows of M^{-l}, l = 0..3
    __shared__ int    s_sp[NSWEEP][12];        // per sweep: v1, v2, bas[0..9]
    __shared__ float  s_ez[NC];

    const int b = blockIdx.x;
    const int tid = threadIdx.x;

    // ---- phase A: init state, GF(2) ring matrices, fused gate matrices ----
    for (int i = tid; i < DIM; i += TPB)
        st[i] = make_float2(i == 0 ? 1.0f : 0.0f, 0.0f);   // sw(0)==0
    if (tid < NC) s_ez[tid] = 0.0f;

    if (tid == 0) {
        // ring map M (amplitude perm C|i> = |M i>), built in application order
        int M[NQ], Mi[NQ];
        for (int r = 0; r < NQ; r++) { M[r] = 1 << r; Mi[r] = 1 << r; }
        for (int q = 0; q < NQ; q++) {           // CNOT(q, q+1), q ascending
            int pc = NQ - 1 - q, pt = NQ - 1 - ((q + 1) % NQ);
            M[pt] ^= M[pc];
        }
        for (int q = NQ - 1; q >= 0; q--) {      // inverse: reversed order
            int pc = NQ - 1 - q, pt = NQ - 1 - ((q + 1) % NQ);
            Mi[pt] ^= Mi[pc];
        }
        // powers M^l and M^{-l}
        int P[NQ], Pi[NQ];
        for (int r = 0; r < NQ; r++) { P[r] = 1 << r; Pi[r] = 1 << r; }
        for (int l = 0; l <= NL; l++) {
            for (int r = 0; r < NQ; r++) s_Mp[l][r] = P[r];
            if (l < NL) for (int r = 0; r < NQ; r++) s_Mip[l][r] = Pi[r];
            int Pn[NQ], Pin[NQ];
            for (int r = 0; r < NQ; r++) {
                int acc = 0, acci = 0;
                for (int s = 0; s < NQ; s++) {
                    if ((M[r]  >> s) & 1) acc  ^= P[s];
                    if ((Mi[r] >> s) & 1) acci ^= Pi[s];
                }
                Pn[r] = acc; Pin[r] = acci;
            }
            for (int r = 0; r < NQ; r++) { P[r] = Pn[r]; Pi[r] = Pin[r]; }
        }
    }

    if (tid < NL * NQ) {   // fused gate U = Rot(w) @ RY(x)
        const int l = tid / NQ, q = tid % NQ;
        const float xh = 0.5f * x[b * NQ + q];
        float sy, cy; sincosf(xh, &sy, &cy);
        const float phi = w[(l * NQ + q) * 3 + 0];
        const float th  = w[(l * NQ + q) * 3 + 1];
        const float om  = w[(l * NQ + q) * 3 + 2];
        float stt, ct; sincosf(0.5f * th, &stt, &ct);
        const float a1 = -0.5f * (phi + om);
        const float a2 =  0.5f * (phi - om);
        float s1, c1, s2, c2;
        sincosf(a1, &s1, &c1);
        sincosf(a2, &s2, &c2);
        const float R00r =  c1 * ct, R00i =  s1 * ct;
        const float R01r = -c2 * stt, R01i = -s2 * stt;
        const float R10r =  c2 * stt, R10i = -s2 * stt;
        const float R11r =  c1 * ct, R11i = -s1 * ct;
        s_g[tid][0] = make_float2( R00r * cy + R01r * sy,  R00i * cy + R01i * sy);
        s_g[tid][1] = make_float2(-R00r * sy + R01r * cy, -R00i * sy + R01i * cy);
        s_g[tid][2] = make_float2( R10r * cy + R11r * sy,  R10i * cy + R11i * sy);
        s_g[tid][3] = make_float2(-R10r * sy + R11r * cy, -R10i * sy + R11i * cy);
    }
    __syncthreads();

    // ---- phase B: per-sweep params (masks + null-space basis) ----
    if (tid < NSWEEP) {
        const int l = tid / 6, k = tid % 6;
        const int pa = NQ - 1 - 2 * k;           // bit of qubit 2k
        const int pb = NQ - 1 - (2 * k + 1);     // bit of qubit 2k+1
        int v1 = 0, v2 = 0;                      // columns of M^{-l}
        for (int r = 0; r < NQ; r++) {
            v1 |= ((s_Mip[l][r] >> pa) & 1) << r;
            v2 |= ((s_Mip[l][r] >> pb) & 1) << r;
        }
        int D1 = s_Mp[l][pa], D2 = s_Mp[l][pb];  // duals: rows of M^l
        const int p1 = __ffs(D1) - 1;
        if ((D2 >> p1) & 1) D2 ^= D1;
        const int p2 = __ffs(D2) - 1;
        if ((D1 >> p2) & 1) D1 ^= D2;
        s_sp[tid][0] = v1;
        s_sp[tid][1] = v2;
        int freeb = 0xFFF & ~((1 << p1) | (1 << p2));
        for (int jj = 0; jj < 10; jj++) {
            const int j = __ffs(freeb) - 1; freeb &= freeb - 1;
            s_sp[tid][2 + jj] = (1 << j) ^ (((D1 >> j) & 1) << p1)
                                         ^ (((D2 >> j) & 1) << p2);
        }
    }
    __syncthreads();

    // ---- phase C: 24 two-qubit sweeps (CNOT rings folded into masks) ----
    for (int swp = 0; swp < NSWEEP; swp++) {
        const int l = swp / 6, k = swp % 6;
        // swizzled pair/quad offsets (sw is XOR-linear)
        const int sv1  = sw(s_sp[swp][0]);
        const int sv2  = sw(s_sp[swp][1]);
        const int sv12 = sv1 ^ sv2;
        const int sb8  = sw(s_sp[swp][10]);
        const int sb9  = sw(s_sp[swp][11]);

        // swizzled base slot for this thread
        int i0b = 0;
#pragma unroll
        for (int jj = 0; jj < 8; jj++)
            i0b ^= ((tid >> jj) & 1) ? s_sp[swp][2 + jj] : 0;
        const int base = sw(i0b);

        const float2* Ga = s_g[l * NQ + 2 * k];
        const float2* Gb = s_g[l * NQ + 2 * k + 1];
        const float2 a0 = Ga[0], a1 = Ga[1], a2 = Ga[2], a3 = Ga[3];
        const float2 b0 = Gb[0], b1 = Gb[1], b2 = Gb[2], b3 = Gb[3];

#pragma unroll 2
        for (int u = 0; u < QUADS / TPB; u++) {
            const int j00 = base ^ ((u & 1) ? sb8 : 0) ^ ((u & 2) ? sb9 : 0);
            const int j01 = j00 ^ sv2;
            const int j10 = j00 ^ sv1;
            const int j11 = j00 ^ sv12;
            float2 s00 = st[j00], s01 = st[j01], s10 = st[j10], s11 = st[j11];
            gate2(b0, b1, b2, b3, s00, s01);   // U_b on qubit 2k+1
            gate2(b0, b1, b2, b3, s10, s11);
            gate2(a0, a1, a2, a3, s00, s10);   // U_a on qubit 2k
            gate2(a0, a1, a2, a3, s01, s11);
            st[j00] = s00; st[j01] = s01; st[j10] = s10; st[j11] = s11;
        }
        __syncthreads();
    }

    // ---- measurement: <Z_c>, final C^4 folded in; iterate slots directly ----
    // parity(i & d) with i = sw^{-1}(s)  ==  parity(s & d~), d~ = (d^d<<4^d<<8)&0xFFF
    int dz[NC];
#pragma unroll
    for (int c = 0; c < NC; c++) {
        const int d = s_Mp[NL][NQ - 1 - c];
        dz[c] = (d ^ (d << 4) ^ (d << 8)) & 0xFFF;
    }

    float ez[NC];
#pragma unroll
    for (int c = 0; c < NC; c++) ez[c] = 0.0f;
    for (int s = tid; s < DIM; s += TPB) {
        const float2 a = st[s];
        const float p = a.x * a.x + a.y * a.y;
#pragma unroll
        for (int c = 0; c < NC; c++)
            ez[c] += (__popc(s & dz[c]) & 1) ? -p : p;
    }
#pragma unroll
    for (int c = 0; c < NC; c++) {
        float v = ez[c];
        for (int o = 16; o > 0; o >>= 1) v += __shfl_down_sync(0xffffffffu, v, o);
        if ((tid & 31) == 0) atomicAdd(&s_ez[c], v);
    }
    __syncthreads();

    // ---- softmax(expz + bias) -> g_probs ----
    if (tid == 0) {
        float z[NC];
        float m = -1e30f;
#pragma unroll
        for (int c = 0; c < NC; c++) {
            z[c] = s_ez[c] + bias[c];
            m = fmaxf(m, z[c]);
        }
        float sum = 0.0f;
#pragma unroll
        for (int c = 0; c < NC; c++) {
            z[c] = expf(z[c] - m);
            sum += z[c];
        }
        const float inv = 1.0f / sum;
#pragma unroll
        for (int c = 0; c < NC; c++) g_probs[b * NC + c] = z[c] * inv;
    }
}

// BatchNorm1d over the batch, per class. 10 blocks x 512 threads.
__global__ __launch_bounds__(BATCH) void bn_kernel(const float* __restrict__ gamma,
                                                   const float* __restrict__ beta,
                                                   float* __restrict__ out) {
    const int c = blockIdx.x;
    const int t = threadIdx.x;  // = batch index

    const float p = g_probs[t * NC + c];

    __shared__ float ssum[BATCH / 32];
    __shared__ float ssq[BATCH / 32];
    float s = p, q = p * p;
    for (int o = 16; o > 0; o >>= 1) {
        s += __shfl_down_sync(0xffffffffu, s, o);
        q += __shfl_down_sync(0xffffffffu, q, o);
    }
    if ((t & 31) == 0) {
        ssum[t >> 5] = s;
        ssq[t >> 5] = q;
    }
    __syncthreads();

    __shared__ float smu, srstd;
    if (t == 0) {
        float S = 0.0f, Q = 0.0f;
#pragma unroll
        for (int i = 0; i < BATCH / 32; i++) { S += ssum[i]; Q += ssq[i]; }
        const float mu = S / (float)BATCH;
        const float var = Q / (float)BATCH - mu * mu;
        smu = mu;
        srstd = rsqrtf(var + BN_EPS);
    }
    __syncthreads();

    out[t * NC + c] = (p - smu) * srstd * gamma[c] + beta[c];
}

extern "C" void kernel_launch(void* const* d_in, const int* in_sizes, int n_in,
                              void* d_out, int out_size) {
    const float* x      = (const float*)d_in[0];  // (512, 12)
    const float* wts    = (const float*)d_in[1];  // (4, 12, 3)
    const float* bias   = (const float*)d_in[2];  // (10,)
    const float* gamma  = (const float*)d_in[3];  // (10,)
    const float* beta   = (const float*)d_in[4];  // (10,)
    float* out = (float*)d_out;                   // (512, 10)

    vqc_kernel<<<BATCH, TPB>>>(x, wts, bias);
    bn_kernel<<<NC, BATCH>>>(gamma, beta, out);
}